// round 1
// baseline (speedup 1.0000x reference)
#include <cuda_runtime.h>
#include <cstdint>

#define NTOK 65536
#define CD   128
#define SEQ  512
#define NGR  128
#define MT   64

// ping-pong activation buffers (device globals: no allocation allowed)
__device__ float g_bufA[(size_t)NTOK * CD];
__device__ float g_bufB[(size_t)NTOK * CD];

// ---------------- projection: h = x @ Wp^T + bp ----------------
// x (NTOK,64), Wp (128,64) -> g_bufA (NTOK,128)
__global__ __launch_bounds__(128) void proj_kernel(const float* __restrict__ x,
                                                   const float* __restrict__ Wp,
                                                   const float* __restrict__ bp) {
    __shared__ float xs[32][68];     // [r][k]
    __shared__ float WT[64][132];    // [k][j]
    const int tid = threadIdx.x;
    const size_t row0 = (size_t)blockIdx.x * 32;

    for (int i = tid; i < 32 * 64; i += 128) {
        int r = i >> 6, k = i & 63;
        xs[r][k] = x[(row0 + (size_t)r) * 64 + k];
    }
    for (int i = tid; i < 128 * 64; i += 128) {
        int j = i >> 6, k = i & 63;
        WT[k][j] = Wp[i];
    }
    __syncthreads();

    const int cg = tid & 15, rg = tid >> 4;   // 16 col groups x 8 row groups
    const int j0 = cg * 8, r0 = rg * 4;
    float acc[4][8];
#pragma unroll
    for (int i = 0; i < 4; ++i)
#pragma unroll
        for (int j = 0; j < 8; ++j) acc[i][j] = 0.f;

#pragma unroll 4
    for (int k = 0; k < 64; ++k) {
        float a4[4], b8[8];
#pragma unroll
        for (int i = 0; i < 4; ++i) a4[i] = xs[r0 + i][k];
        float4 blo = *(const float4*)&WT[k][j0];
        float4 bhi = *(const float4*)&WT[k][j0 + 4];
        b8[0]=blo.x; b8[1]=blo.y; b8[2]=blo.z; b8[3]=blo.w;
        b8[4]=bhi.x; b8[5]=bhi.y; b8[6]=bhi.z; b8[7]=bhi.w;
#pragma unroll
        for (int i = 0; i < 4; ++i)
#pragma unroll
            for (int j = 0; j < 8; ++j)
                acc[i][j] = fmaf(a4[i], b8[j], acc[i][j]);
    }
#pragma unroll
    for (int j = 0; j < 8; ++j) {
        float bj = bp[j0 + j];
#pragma unroll
        for (int i = 0; i < 4; ++i)
            g_bufA[(row0 + r0 + i) * CD + j0 + j] = acc[i][j] + bj;
    }
}

// ---------------- conv: backward-stable exponential recurrence ----------------
// JAX conv is cross-correlation: effective causal weight on lag s is
//   c[s] = exp(-(255-s)/tau)/(S+1e-8)   (GROWS with lag s)
// so y[l] = z[l]*scale with z[l] = sum_{m=0..255} rho^m x[l-255+m], rho=e^{-1/tau}<1.
// Stable backward recurrence: z[l-1] = rho*z[l] + x[l-256] - rho^256 * x[l].
// Grid: (NGR*4) blocks (4 L-chunks per graph) x 128 threads (one per channel).
__global__ __launch_bounds__(128) void conv_kernel(const float* __restrict__ log_tau_d) {
    const int b = blockIdx.x >> 2;
    const int q = blockIdx.x & 3;
    const int c = threadIdx.x;

    float tau  = fmaxf(expf(log_tau_d[c]), 0.001f);
    float it   = 1.0f / tau;
    float rho  = expf(-it);
    float rhoK = expf(-256.0f * it);
    float den  = 1.0f - rho;
    float S    = (den > 1e-20f) ? (1.0f - rhoK) / den : 256.0f;
    float scale = 1.0f / (S + 1e-8f);

    const float* xp = g_bufA + (size_t)b * SEQ * CD + c;
    float*       yp = g_bufB + (size_t)b * SEQ * CD + c;

    const int l_top = q * 128 + 127;
    const int base  = l_top - 255;
    float acc = 0.f;
#pragma unroll 8
    for (int j = 255; j >= 0; --j) {
        int idx = base + j;
        float xv = (idx >= 0) ? xp[idx * CD] : 0.f;
        acc = fmaf(rho, acc, xv);
    }
    int l = l_top;
#pragma unroll 8
    for (int n = 0; n < 128; ++n, --l) {
        yp[l * CD] = acc * scale;
        float xold = (l >= 256) ? xp[(l - 256) * CD] : 0.f;
        float xtop = xp[l * CD];
        acc = fmaf(rho, acc, fmaf(-rhoK, xtop, xold));
    }
}

// ---------------- fused MLP: gates GEMM + GLU + out GEMM + residual + LN ----------------
// reads g_bufB (conv out), writes g_bufA (depth out)
#define MLP_SMEM_BYTES ((128 * 68 + 256 * 68 + 16 * 264) * 4)

__global__ __launch_bounds__(256) void mlp_kernel(const float* __restrict__ W_in,
                                                  const float* __restrict__ b_in,
                                                  const float* __restrict__ W_out,
                                                  const float* __restrict__ b_out,
                                                  const float* __restrict__ gamma,
                                                  const float* __restrict__ beta) {
    extern __shared__ float sm[];
    float* ysT = sm;                      // [c][r], stride 68, c<128
    float* gT  = sm + 128 * 68;           // [j][r], stride 68, j<256
    float* Wk  = sm + (128 + 256) * 68;   // [kk][j], stride 264, kk<16
    const int tid = threadIdx.x;
    const size_t row0 = (size_t)blockIdx.x * MT;

    // load y tile transposed
    for (int i = tid; i < MT * 128; i += 256) {
        int r = i >> 7, c = i & 127;
        ysT[c * 68 + r] = g_bufB[(row0 + r) * CD + c];
    }
    __syncthreads();

    // ---- GEMM1: gates[r][j] = sum_c y[r][c] W_in[j][c], j in [0,256) ----
    const int cg = tid & 31, rg = tid >> 5;    // 32 col groups x 8 row groups
    const int j0 = cg * 8, r0 = rg * 8;
    float acc[8][8];
#pragma unroll
    for (int i = 0; i < 8; ++i)
#pragma unroll
        for (int j = 0; j < 8; ++j) acc[i][j] = 0.f;

    for (int k0 = 0; k0 < 128; k0 += 16) {
        __syncthreads();
        for (int i = tid; i < 256 * 16; i += 256) {
            int j = i >> 4, kk = i & 15;
            Wk[kk * 264 + j] = W_in[j * 128 + k0 + kk];
        }
        __syncthreads();
#pragma unroll
        for (int kk = 0; kk < 16; ++kk) {
            int k = k0 + kk;
            float4 a0 = *(const float4*)&ysT[k * 68 + r0];
            float4 a1 = *(const float4*)&ysT[k * 68 + r0 + 4];
            float4 b0 = *(const float4*)&Wk[kk * 264 + j0];
            float4 b1 = *(const float4*)&Wk[kk * 264 + j0 + 4];
            float a8[8] = {a0.x,a0.y,a0.z,a0.w,a1.x,a1.y,a1.z,a1.w};
            float b8[8] = {b0.x,b0.y,b0.z,b0.w,b1.x,b1.y,b1.z,b1.w};
#pragma unroll
            for (int i = 0; i < 8; ++i)
#pragma unroll
                for (int j = 0; j < 8; ++j)
                    acc[i][j] = fmaf(a8[i], b8[j], acc[i][j]);
        }
    }
    // write gates (+bias), transposed [j][r]
#pragma unroll
    for (int j = 0; j < 8; ++j) {
        float bj = b_in[j0 + j];
        float4 w0 = make_float4(acc[0][j]+bj, acc[1][j]+bj, acc[2][j]+bj, acc[3][j]+bj);
        float4 w1 = make_float4(acc[4][j]+bj, acc[5][j]+bj, acc[6][j]+bj, acc[7][j]+bj);
        *(float4*)&gT[(j0 + j) * 68 + r0]     = w0;
        *(float4*)&gT[(j0 + j) * 68 + r0 + 4] = w1;
    }
    __syncthreads();

    // ---- GLU: u[c][r] = a * sigmoid(g) in place (a=cols 0..127, g=cols 128..255) ----
    for (int i = tid; i < 128 * MT; i += 256) {
        int c = i >> 6, r = i & 63;
        float av = gT[c * 68 + r];
        float gv = gT[(c + 128) * 68 + r];
        gT[c * 68 + r] = av / (1.0f + expf(-gv));
    }
    __syncthreads();

    // ---- GEMM2: y2[r][j] = sum_c u[r][c] W_out[j][c], j in [0,128) ----
    const int cg2 = tid & 15, rg2 = tid >> 4;   // 16 col groups x 16 row groups
    const int j2 = cg2 * 8, r2 = rg2 * 4;
    float acc2[4][8];
#pragma unroll
    for (int i = 0; i < 4; ++i)
#pragma unroll
        for (int j = 0; j < 8; ++j) acc2[i][j] = 0.f;

    for (int k0 = 0; k0 < 128; k0 += 16) {
        __syncthreads();
        for (int i = tid; i < 128 * 16; i += 256) {
            int j = i >> 4, kk = i & 15;
            Wk[kk * 264 + j] = W_out[j * 128 + k0 + kk];
        }
        __syncthreads();
#pragma unroll
        for (int kk = 0; kk < 16; ++kk) {
            int k = k0 + kk;
            float4 a0 = *(const float4*)&gT[k * 68 + r2];
            float4 b0 = *(const float4*)&Wk[kk * 264 + j2];
            float4 b1 = *(const float4*)&Wk[kk * 264 + j2 + 4];
            float a4[4] = {a0.x,a0.y,a0.z,a0.w};
            float b8[8] = {b0.x,b0.y,b0.z,b0.w,b1.x,b1.y,b1.z,b1.w};
#pragma unroll
            for (int i = 0; i < 4; ++i)
#pragma unroll
                for (int j = 0; j < 8; ++j)
                    acc2[i][j] = fmaf(a4[i], b8[j], acc2[i][j]);
        }
    }
    // z = y2 + b_out + residual -> store into free g-half region of gT
#pragma unroll
    for (int j = 0; j < 8; ++j) {
        float bj = b_out[j2 + j];
#pragma unroll
        for (int i = 0; i < 4; ++i) {
            float zv = acc2[i][j] + bj + ysT[(j2 + j) * 68 + (r2 + i)];
            gT[(128 + j2 + j) * 68 + (r2 + i)] = zv;
        }
    }
    __syncthreads();

    // ---- LayerNorm per row (over 128 channels), write to g_bufA ----
    const int warp = tid >> 5, lane = tid & 31;
    for (int r = warp; r < MT; r += 8) {
        float v[4]; float s = 0.f;
#pragma unroll
        for (int i = 0; i < 4; ++i) {
            v[i] = gT[(128 + lane + i * 32) * 68 + r];
            s += v[i];
        }
#pragma unroll
        for (int off = 16; off; off >>= 1) s += __shfl_xor_sync(0xffffffffu, s, off);
        float mu = s * (1.0f / 128.0f);
        float vs = 0.f;
#pragma unroll
        for (int i = 0; i < 4; ++i) { float d = v[i] - mu; vs += d * d; }
#pragma unroll
        for (int off = 16; off; off >>= 1) vs += __shfl_xor_sync(0xffffffffu, vs, off);
        float rstd = rsqrtf(vs * (1.0f / 128.0f) + 1e-5f);
#pragma unroll
        for (int i = 0; i < 4; ++i) {
            int ch = lane + i * 32;
            g_bufA[(row0 + r) * CD + ch] = (v[i] - mu) * rstd * gamma[ch] + beta[ch];
        }
    }
}

// ---------------- final mean over L ----------------
__global__ __launch_bounds__(512) void mean_kernel(float* __restrict__ out) {
    __shared__ float part[4][128];
    const int b  = blockIdx.x;
    const int c  = threadIdx.x & 127;
    const int lq = threadIdx.x >> 7;
    const float* p = g_bufA + (size_t)b * SEQ * CD + c;
    float s = 0.f;
    for (int l = lq * 128; l < lq * 128 + 128; ++l) s += p[l * CD];
    part[lq][c] = s;
    __syncthreads();
    if (lq == 0)
        out[b * CD + c] = (part[0][c] + part[1][c] + part[2][c] + part[3][c]) * (1.0f / 512.0f);
}

extern "C" void kernel_launch(void* const* d_in, const int* in_sizes, int n_in,
                              void* d_out, int out_size) {
    const float* x     = (const float*)d_in[0];
    // d_in[1] = batch (int32) — unused by the reference computation
    const float* Wp    = (const float*)d_in[2];
    const float* bp    = (const float*)d_in[3];
    const float* ltau  = (const float*)d_in[4];
    const float* W_in  = (const float*)d_in[5];
    const float* b_in  = (const float*)d_in[6];
    const float* W_out = (const float*)d_in[7];
    const float* b_out = (const float*)d_in[8];
    const float* gamma = (const float*)d_in[9];
    const float* beta  = (const float*)d_in[10];
    float* out = (float*)d_out;

    cudaFuncSetAttribute(mlp_kernel, cudaFuncAttributeMaxDynamicSharedMemorySize,
                         MLP_SMEM_BYTES);

    proj_kernel<<<NTOK / 32, 128>>>(x, Wp, bp);
    for (int d = 0; d < 3; ++d) {
        conv_kernel<<<NGR * 4, 128>>>(ltau + d * 128);
        mlp_kernel<<<NTOK / MT, 256, MLP_SMEM_BYTES>>>(
            W_in + (size_t)d * 256 * 128, b_in + d * 256,
            W_out + (size_t)d * 128 * 128, b_out + d * 128,
            gamma + d * 128, beta + d * 128);
    }
    mean_kernel<<<NGR, 512>>>(out);
}

// round 3
// speedup vs baseline: 1.1521x; 1.1521x over previous
#include <cuda_runtime.h>
#include <cstdint>

#define NTOK 65536
#define CD   128
#define SEQ  512
#define NGR  128
#define MT   64

// ping-pong activation buffers (device globals: no allocation allowed)
__device__ float g_bufA[(size_t)NTOK * CD];
__device__ float g_bufB[(size_t)NTOK * CD];

__device__ __forceinline__ void ffma2(unsigned long long& d,
                                      unsigned long long a,
                                      unsigned long long b) {
    asm("fma.rn.f32x2 %0, %1, %2, %0;" : "+l"(d) : "l"(a), "l"(b));
}
__device__ __forceinline__ unsigned long long rep2(float v) {
    unsigned long long r;
    unsigned int u = __float_as_uint(v);
    asm("mov.b64 %0, {%1, %1};" : "=l"(r) : "r"(u));
    return r;
}

// ---------------- projection: h = x @ Wp^T + bp ----------------
// x (NTOK,64), Wp (128,64) -> g_bufA (NTOK,128)
__global__ __launch_bounds__(128) void proj_kernel(const float* __restrict__ x,
                                                   const float* __restrict__ Wp,
                                                   const float* __restrict__ bproj) {
    __shared__ float xs2[64 * 36];   // [k][r], stride 36
    __shared__ float WT[64 * 132];   // [k][j], stride 132
    const int tid = threadIdx.x;
    const size_t row0 = (size_t)blockIdx.x * 32;

    for (int i = tid; i < 32 * 64; i += 128) {
        int r = i >> 6, k = i & 63;
        xs2[k * 36 + r] = x[(row0 + (size_t)r) * 64 + k];
    }
    for (int i = tid; i < 128 * 64; i += 128) {
        int j = i >> 6, k = i & 63;
        WT[k * 132 + j] = Wp[i];
    }
    __syncthreads();

    const int cg = tid & 31, rg = tid >> 5;   // 32 col groups x 4 row groups
    const int j0 = cg * 4, r0 = rg * 8;
    unsigned long long acc[4][4];             // [row-pair][col]
#pragma unroll
    for (int i = 0; i < 4; ++i)
#pragma unroll
        for (int j = 0; j < 4; ++j) acc[i][j] = 0ull;

#pragma unroll 8
    for (int k = 0; k < 64; ++k) {
        ulonglong2 a0 = *(const ulonglong2*)&xs2[k * 36 + r0];
        ulonglong2 a1 = *(const ulonglong2*)&xs2[k * 36 + r0 + 4];
        float4 b = *(const float4*)&WT[k * 132 + j0];
        unsigned long long ap[4] = {a0.x, a0.y, a1.x, a1.y};
        unsigned long long bp4[4] = {rep2(b.x), rep2(b.y), rep2(b.z), rep2(b.w)};
#pragma unroll
        for (int ip = 0; ip < 4; ++ip)
#pragma unroll
            for (int j = 0; j < 4; ++j)
                ffma2(acc[ip][j], ap[ip], bp4[j]);
    }
#pragma unroll
    for (int j = 0; j < 4; ++j) {
        float bj = bproj[j0 + j];
#pragma unroll
        for (int ip = 0; ip < 4; ++ip) {
            float2 f = *(float2*)&acc[ip][j];
            g_bufA[(row0 + r0 + 2 * ip) * CD + j0 + j]     = f.x + bj;
            g_bufA[(row0 + r0 + 2 * ip + 1) * CD + j0 + j] = f.y + bj;
        }
    }
}

// ---------------- conv: backward-stable exponential recurrence (round-1 verbatim) ----------------
__global__ __launch_bounds__(128) void conv_kernel(const float* __restrict__ log_tau_d) {
    const int b = blockIdx.x >> 2;
    const int q = blockIdx.x & 3;
    const int c = threadIdx.x;

    float tau  = fmaxf(expf(log_tau_d[c]), 0.001f);
    float it   = 1.0f / tau;
    float rho  = expf(-it);
    float rhoK = expf(-256.0f * it);
    float den  = 1.0f - rho;
    float S    = (den > 1e-20f) ? (1.0f - rhoK) / den : 256.0f;
    float scale = 1.0f / (S + 1e-8f);

    const float* xp = g_bufA + (size_t)b * SEQ * CD + c;
    float*       yp = g_bufB + (size_t)b * SEQ * CD + c;

    const int l_top = q * 128 + 127;
    const int base  = l_top - 255;
    float acc = 0.f;
#pragma unroll 8
    for (int j = 255; j >= 0; --j) {
        int idx = base + j;
        float xv = (idx >= 0) ? xp[idx * CD] : 0.f;
        acc = fmaf(rho, acc, xv);
    }
    int l = l_top;
#pragma unroll 8
    for (int n = 0; n < 128; ++n, --l) {
        yp[l * CD] = acc * scale;
        float xold = (l >= 256) ? xp[(l - 256) * CD] : 0.f;
        float xtop = xp[l * CD];
        acc = fmaf(rho, acc, fmaf(-rhoK, xtop, xold));
    }
}

// ---------------- fused MLP: gates GEMM + GLU + out GEMM + residual + LN ----------------
// SMEM layouts identical to round 1: ysT[c][r] s68, gT[j][r] s68, Wk[kk][j] s264
#define MLP_SMEM_BYTES ((128 * 68 + 256 * 68 + 16 * 264) * 4)

__global__ __launch_bounds__(256) void mlp_kernel(const float* __restrict__ W_in,
                                                  const float* __restrict__ b_in,
                                                  const float* __restrict__ W_out,
                                                  const float* __restrict__ b_out,
                                                  const float* __restrict__ gamma,
                                                  const float* __restrict__ beta) {
    extern __shared__ float sm[];
    float* ysT = sm;                      // [c][r], stride 68, c<128
    float* gT  = sm + 128 * 68;           // [j][r], stride 68, j<256
    float* Wk  = sm + (128 + 256) * 68;   // [kk][j], stride 264, kk<16
    const int tid = threadIdx.x;
    const size_t row0 = (size_t)blockIdx.x * MT;

    // load y tile transposed (round-1 verbatim)
    for (int i = tid; i < MT * 128; i += 256) {
        int r = i >> 7, c = i & 127;
        ysT[c * 68 + r] = g_bufB[(row0 + r) * CD + c];
    }
    __syncthreads();

    // ---- GEMM1: gates[r][j] = sum_c y[r][c] W_in[j][c], j in [0,256) ----
    const int cg = tid & 31, rg = tid >> 5;    // 32 col groups x 8 row groups
    const int j0 = cg * 8, r0 = rg * 8;
    unsigned long long acc[4][8];              // [row-pair][col]
#pragma unroll
    for (int i = 0; i < 4; ++i)
#pragma unroll
        for (int j = 0; j < 8; ++j) acc[i][j] = 0ull;

    for (int k0 = 0; k0 < 128; k0 += 16) {
        __syncthreads();
        for (int i = tid; i < 256 * 16; i += 256) {
            int j = i >> 4, kk = i & 15;
            Wk[kk * 264 + j] = W_in[j * 128 + k0 + kk];
        }
        __syncthreads();
#pragma unroll
        for (int kk = 0; kk < 16; ++kk) {
            int k = k0 + kk;
            ulonglong2 a0 = *(const ulonglong2*)&ysT[k * 68 + r0];
            ulonglong2 a1 = *(const ulonglong2*)&ysT[k * 68 + r0 + 4];
            float4 blo = *(const float4*)&Wk[kk * 264 + j0];
            float4 bhi = *(const float4*)&Wk[kk * 264 + j0 + 4];
            unsigned long long ap[4] = {a0.x, a0.y, a1.x, a1.y};
            unsigned long long bp8[8] = {rep2(blo.x), rep2(blo.y), rep2(blo.z), rep2(blo.w),
                                         rep2(bhi.x), rep2(bhi.y), rep2(bhi.z), rep2(bhi.w)};
#pragma unroll
            for (int ip = 0; ip < 4; ++ip)
#pragma unroll
                for (int j = 0; j < 8; ++j)
                    ffma2(acc[ip][j], ap[ip], bp8[j]);
        }
    }
    __syncthreads();
    // write gates (+bias), transposed [j][r] — row pairs are contiguous in r
#pragma unroll
    for (int j = 0; j < 8; ++j) {
        float bj = b_in[j0 + j];
#pragma unroll
        for (int ip = 0; ip < 4; ++ip) {
            float2 f = *(float2*)&acc[ip][j];
            f.x += bj; f.y += bj;
            *(float2*)&gT[(j0 + j) * 68 + r0 + 2 * ip] = f;
        }
    }
    __syncthreads();

    // ---- GLU: u[c][r] = a * sigmoid(g) in place (round-1 verbatim) ----
    for (int i = tid; i < 128 * MT; i += 256) {
        int c = i >> 6, r = i & 63;
        float av = gT[c * 68 + r];
        float gv = gT[(c + 128) * 68 + r];
        gT[c * 68 + r] = av / (1.0f + expf(-gv));
    }
    __syncthreads();

    // ---- GEMM2: y2[r][j] = sum_c u[r][c] W_out[j][c], j in [0,128) ----
    const int cg2 = tid & 31, rg2 = tid >> 5;  // 32 col groups x 8 row groups
    const int j2 = cg2 * 4, r2 = rg2 * 8;
    unsigned long long acc2[4][4];             // [row-pair][col]
#pragma unroll
    for (int i = 0; i < 4; ++i)
#pragma unroll
        for (int j = 0; j < 4; ++j) acc2[i][j] = 0ull;

    for (int k0 = 0; k0 < 128; k0 += 16) {
        __syncthreads();
        for (int i = tid; i < 128 * 16; i += 256) {
            int j = i >> 4, kk = i & 15;
            Wk[kk * 264 + j] = W_out[j * 128 + k0 + kk];
        }
        __syncthreads();
#pragma unroll
        for (int kk = 0; kk < 16; ++kk) {
            int k = k0 + kk;
            ulonglong2 a0 = *(const ulonglong2*)&gT[k * 68 + r2];
            ulonglong2 a1 = *(const ulonglong2*)&gT[k * 68 + r2 + 4];
            float4 b = *(const float4*)&Wk[kk * 264 + j2];
            unsigned long long ap[4] = {a0.x, a0.y, a1.x, a1.y};
            unsigned long long bp4[4] = {rep2(b.x), rep2(b.y), rep2(b.z), rep2(b.w)};
#pragma unroll
            for (int ip = 0; ip < 4; ++ip)
#pragma unroll
                for (int j = 0; j < 4; ++j)
                    ffma2(acc2[ip][j], ap[ip], bp4[j]);
        }
    }
    // z = y2 + b_out + residual -> dead gate half of gT (row pairs contiguous)
#pragma unroll
    for (int j = 0; j < 4; ++j) {
        float bj = b_out[j2 + j];
#pragma unroll
        for (int ip = 0; ip < 4; ++ip) {
            float2 f = *(float2*)&acc2[ip][j];
            float2 res = *(const float2*)&ysT[(j2 + j) * 68 + r2 + 2 * ip];
            float2 z;
            z.x = f.x + bj + res.x;
            z.y = f.y + bj + res.y;
            *(float2*)&gT[(128 + j2 + j) * 68 + r2 + 2 * ip] = z;
        }
    }
    __syncthreads();

    // ---- LayerNorm per row (round-1 verbatim) ----
    const int warp = tid >> 5, lane = tid & 31;
    for (int r = warp; r < MT; r += 8) {
        float v[4]; float s = 0.f;
#pragma unroll
        for (int i = 0; i < 4; ++i) {
            v[i] = gT[(128 + lane + i * 32) * 68 + r];
            s += v[i];
        }
#pragma unroll
        for (int off = 16; off; off >>= 1) s += __shfl_xor_sync(0xffffffffu, s, off);
        float mu = s * (1.0f / 128.0f);
        float vs = 0.f;
#pragma unroll
        for (int i = 0; i < 4; ++i) { float d = v[i] - mu; vs += d * d; }
#pragma unroll
        for (int off = 16; off; off >>= 1) vs += __shfl_xor_sync(0xffffffffu, vs, off);
        float rstd = rsqrtf(vs * (1.0f / 128.0f) + 1e-5f);
#pragma unroll
        for (int i = 0; i < 4; ++i) {
            int ch = lane + i * 32;
            g_bufA[(row0 + r) * CD + ch] = (v[i] - mu) * rstd * gamma[ch] + beta[ch];
        }
    }
}

// ---------------- final mean over L (round-1 verbatim) ----------------
__global__ __launch_bounds__(512) void mean_kernel(float* __restrict__ out) {
    __shared__ float part[4][128];
    const int b  = blockIdx.x;
    const int c  = threadIdx.x & 127;
    const int lq = threadIdx.x >> 7;
    const float* p = g_bufA + (size_t)b * SEQ * CD + c;
    float s = 0.f;
    for (int l = lq * 128; l < lq * 128 + 128; ++l) s += p[l * CD];
    part[lq][c] = s;
    __syncthreads();
    if (lq == 0)
        out[b * CD + c] = (part[0][c] + part[1][c] + part[2][c] + part[3][c]) * (1.0f / 512.0f);
}

extern "C" void kernel_launch(void* const* d_in, const int* in_sizes, int n_in,
                              void* d_out, int out_size) {
    const float* x     = (const float*)d_in[0];
    const float* Wp    = (const float*)d_in[2];
    const float* bp    = (const float*)d_in[3];
    const float* ltau  = (const float*)d_in[4];
    const float* W_in  = (const float*)d_in[5];
    const float* b_in  = (const float*)d_in[6];
    const float* W_out = (const float*)d_in[7];
    const float* b_out = (const float*)d_in[8];
    const float* gamma = (const float*)d_in[9];
    const float* beta  = (const float*)d_in[10];
    float* out = (float*)d_out;

    cudaFuncSetAttribute(mlp_kernel, cudaFuncAttributeMaxDynamicSharedMemorySize,
                         MLP_SMEM_BYTES);

    proj_kernel<<<NTOK / 32, 128>>>(x, Wp, bp);
    for (int d = 0; d < 3; ++d) {
        conv_kernel<<<NGR * 4, 128>>>(ltau + d * 128);
        mlp_kernel<<<NTOK / MT, 256, MLP_SMEM_BYTES>>>(
            W_in + (size_t)d * 256 * 128, b_in + d * 256,
            W_out + (size_t)d * 128 * 128, b_out + d * 128,
            gamma + d * 128, beta + d * 128);
    }
    mean_kernel<<<NGR, 512>>>(out);
}

// round 6
// speedup vs baseline: 2.1603x; 1.8751x over previous
#include <cuda_runtime.h>
#include <cuda_bf16.h>
#include <cstdint>

#define NTOK 65536
#define CD   128
#define SEQ  512
#define NGR  128

__device__ float g_bufA[(size_t)NTOK * CD];
__device__ float g_bufB[(size_t)NTOK * CD];

// bf16 hi/lo weight images (row-major [n][k], k=128)
__device__ __nv_bfloat16 g_WinH[3][256 * 128];
__device__ __nv_bfloat16 g_WinL[3][256 * 128];
__device__ __nv_bfloat16 g_WoutH[3][128 * 128];
__device__ __nv_bfloat16 g_WoutL[3][128 * 128];

__device__ __forceinline__ unsigned int smem_u32(const void* p) {
    unsigned int a;
    asm("{ .reg .u64 t; cvta.to.shared.u64 t, %1; cvt.u32.u64 %0, t; }" : "=r"(a) : "l"(p));
    return a;
}

#define LDSM4(v, addr) \
    asm volatile("ldmatrix.sync.aligned.m8n8.x4.shared.b16 {%0,%1,%2,%3}, [%4];" \
                 : "=r"((v).x), "=r"((v).y), "=r"((v).z), "=r"((v).w) : "r"(addr))

#define MMA_BF16(d, a, b0, b1) \
    asm volatile("mma.sync.aligned.m16n8k16.row.col.f32.bf16.bf16.f32 " \
                 "{%0,%1,%2,%3}, {%4,%5,%6,%7}, {%8,%9}, {%0,%1,%2,%3};" \
                 : "+f"((d)[0]), "+f"((d)[1]), "+f"((d)[2]), "+f"((d)[3]) \
                 : "r"((a).x), "r"((a).y), "r"((a).z), "r"((a).w), "r"(b0), "r"(b1))

// ---------------- weight staging: fp32 -> bf16 hi/lo ----------------
__global__ __launch_bounds__(256) void stage_w_kernel(const float* __restrict__ W_in,
                                                      const float* __restrict__ W_out) {
    const int d = blockIdx.x;
    const int tid = threadIdx.x;
    for (int i = tid; i < 256 * 128; i += 256) {
        float v = W_in[d * 256 * 128 + i];
        __nv_bfloat16 h = __float2bfloat16(v);
        g_WinH[d][i] = h;
        g_WinL[d][i] = __float2bfloat16(v - __bfloat162float(h));
    }
    for (int i = tid; i < 128 * 128; i += 256) {
        float v = W_out[d * 128 * 128 + i];
        __nv_bfloat16 h = __float2bfloat16(v);
        g_WoutH[d][i] = h;
        g_WoutL[d][i] = __float2bfloat16(v - __bfloat162float(h));
    }
}

// ---------------- projection (R3 verbatim, FFMA2) ----------------
__device__ __forceinline__ void ffma2(unsigned long long& d,
                                      unsigned long long a,
                                      unsigned long long b) {
    asm("fma.rn.f32x2 %0, %1, %2, %0;" : "+l"(d) : "l"(a), "l"(b));
}
__device__ __forceinline__ unsigned long long rep2(float v) {
    unsigned long long r;
    unsigned int u = __float_as_uint(v);
    asm("mov.b64 %0, {%1, %1};" : "=l"(r) : "r"(u));
    return r;
}
__global__ __launch_bounds__(128) void proj_kernel(const float* __restrict__ x,
                                                   const float* __restrict__ Wp,
                                                   const float* __restrict__ bproj) {
    __shared__ float xs2[64 * 36];
    __shared__ float WT[64 * 132];
    const int tid = threadIdx.x;
    const size_t row0 = (size_t)blockIdx.x * 32;

    for (int i = tid; i < 32 * 64; i += 128) {
        int r = i >> 6, k = i & 63;
        xs2[k * 36 + r] = x[(row0 + (size_t)r) * 64 + k];
    }
    for (int i = tid; i < 128 * 64; i += 128) {
        int j = i >> 6, k = i & 63;
        WT[k * 132 + j] = Wp[i];
    }
    __syncthreads();

    const int cg = tid & 31, rg = tid >> 5;
    const int j0 = cg * 4, r0 = rg * 8;
    unsigned long long acc[4][4];
#pragma unroll
    for (int i = 0; i < 4; ++i)
#pragma unroll
        for (int j = 0; j < 4; ++j) acc[i][j] = 0ull;

#pragma unroll 8
    for (int k = 0; k < 64; ++k) {
        ulonglong2 a0 = *(const ulonglong2*)&xs2[k * 36 + r0];
        ulonglong2 a1 = *(const ulonglong2*)&xs2[k * 36 + r0 + 4];
        float4 b = *(const float4*)&WT[k * 132 + j0];
        unsigned long long ap[4] = {a0.x, a0.y, a1.x, a1.y};
        unsigned long long bp4[4] = {rep2(b.x), rep2(b.y), rep2(b.z), rep2(b.w)};
#pragma unroll
        for (int ip = 0; ip < 4; ++ip)
#pragma unroll
            for (int j = 0; j < 4; ++j)
                ffma2(acc[ip][j], ap[ip], bp4[j]);
    }
#pragma unroll
    for (int j = 0; j < 4; ++j) {
        float bj = bproj[j0 + j];
#pragma unroll
        for (int ip = 0; ip < 4; ++ip) {
            float2 f = *(float2*)&acc[ip][j];
            g_bufA[(row0 + r0 + 2 * ip) * CD + j0 + j]     = f.x + bj;
            g_bufA[(row0 + r0 + 2 * ip + 1) * CD + j0 + j] = f.y + bj;
        }
    }
}

// ---------------- conv (R1 verbatim) ----------------
__global__ __launch_bounds__(128) void conv_kernel(const float* __restrict__ log_tau_d) {
    const int b = blockIdx.x >> 2;
    const int q = blockIdx.x & 3;
    const int c = threadIdx.x;

    float tau  = fmaxf(expf(log_tau_d[c]), 0.001f);
    float it   = 1.0f / tau;
    float rho  = expf(-it);
    float rhoK = expf(-256.0f * it);
    float den  = 1.0f - rho;
    float S    = (den > 1e-20f) ? (1.0f - rhoK) / den : 256.0f;
    float scale = 1.0f / (S + 1e-8f);

    const float* xp = g_bufA + (size_t)b * SEQ * CD + c;
    float*       yp = g_bufB + (size_t)b * SEQ * CD + c;

    const int l_top = q * 128 + 127;
    const int base  = l_top - 255;
    float acc = 0.f;
#pragma unroll 8
    for (int j = 255; j >= 0; --j) {
        int idx = base + j;
        float xv = (idx >= 0) ? xp[idx * CD] : 0.f;
        acc = fmaf(rho, acc, xv);
    }
    int l = l_top;
#pragma unroll 8
    for (int n = 0; n < 128; ++n, --l) {
        yp[l * CD] = acc * scale;
        float xold = (l >= 256) ? xp[(l - 256) * CD] : 0.f;
        float xtop = xp[l * CD];
        acc = fmaf(rho, acc, fmaf(-rhoK, xtop, xold));
    }
}

// ---------------- mma.sync fused MLP ----------------
#define SM_YH   0
#define SM_YL   17408
#define SM_WH   34816
#define SM_WL   69632
#define SM_UH   104448
#define SM_UL   121856
#define SM_YRES 139264
#define SM_ZB   173056
#define MMA_SMEM_BYTES 206848

__device__ __forceinline__ void do_gemm(char* smem, unsigned sb,
                                        unsigned aH, unsigned aL,
                                        int r0, int n0w, int lane,
                                        float acc[8][4]) {
#pragma unroll
    for (int ks = 0; ks < 8; ++ks) {
        const int k0 = ks * 16;
        unsigned aoff = (unsigned)(r0 + (lane & 15)) * 272u
                      + (unsigned)(k0 + ((lane & 16) >> 1)) * 2u;
        uint4 ah, al;
        LDSM4(ah, sb + aH + aoff);
        LDSM4(al, sb + aL + aoff);
        unsigned brow = (unsigned)(n0w + (lane & 7) + ((lane & 16) >> 1));
        unsigned bcol = (unsigned)(k0 + (lane & 8));
#pragma unroll
        for (int nb = 0; nb < 4; ++nb) {
            unsigned boff = (brow + nb * 16u) * 272u + bcol * 2u;
            uint4 bh, bl;
            LDSM4(bh, sb + SM_WH + boff);
            LDSM4(bl, sb + SM_WL + boff);
            MMA_BF16(acc[nb * 2],     ah, bh.x, bh.y);
            MMA_BF16(acc[nb * 2],     ah, bl.x, bl.y);
            MMA_BF16(acc[nb * 2],     al, bh.x, bh.y);
            MMA_BF16(acc[nb * 2 + 1], ah, bh.z, bh.w);
            MMA_BF16(acc[nb * 2 + 1], ah, bl.z, bl.w);
            MMA_BF16(acc[nb * 2 + 1], al, bh.z, bh.w);
        }
    }
}

__device__ __forceinline__ void copy_w(char* smem, int tid,
                                       const __nv_bfloat16* __restrict__ srcH,
                                       const __nv_bfloat16* __restrict__ srcL) {
#pragma unroll
    for (int t = 0; t < 8; ++t) {
        int i = tid + t * 256;            // uint4 index over 128 rows x 16 chunks
        int r = i >> 4, c = i & 15;
        *(uint4*)(smem + SM_WH + r * 272 + c * 16) = ((const uint4*)srcH)[i];
        *(uint4*)(smem + SM_WL + r * 272 + c * 16) = ((const uint4*)srcL)[i];
    }
}

__global__ __launch_bounds__(256) void mlp_mma_kernel(int depth,
                                                      const float* __restrict__ b_in,
                                                      const float* __restrict__ b_out,
                                                      const float* __restrict__ gamma,
                                                      const float* __restrict__ beta) {
    extern __shared__ char smem[];
    const unsigned sb = smem_u32(smem);
    const int tid = threadIdx.x;
    const int wid = tid >> 5, lane = tid & 31;
    const int wr = wid >> 1, wc = wid & 1;
    const int r0 = wr * 16;               // warp row base
    const int n0w = wc * 64;              // warp col base
    const size_t row0 = (size_t)blockIdx.x * 64;

    float* yres = (float*)(smem + SM_YRES);
    float* zbuf = (float*)(smem + SM_ZB);

    // ---- load Y tile: fp32 residual copy + bf16 hi/lo tiles ----
#pragma unroll
    for (int t = 0; t < 16; ++t) {
        int idx = tid + t * 256;          // pair index over 64 x 64
        int r = idx >> 6, kp = idx & 63;
        float2 y2 = *(const float2*)&g_bufB[(row0 + r) * CD + 2 * kp];
        __nv_bfloat16 h0 = __float2bfloat16(y2.x), h1 = __float2bfloat16(y2.y);
        __nv_bfloat16 l0 = __float2bfloat16(y2.x - __bfloat162float(h0));
        __nv_bfloat16 l1 = __float2bfloat16(y2.y - __bfloat162float(h1));
        __nv_bfloat162 hp = __halves2bfloat162(h0, h1);
        __nv_bfloat162 lp = __halves2bfloat162(l0, l1);
        *(unsigned*)(smem + SM_YH + r * 272 + kp * 4) = *(unsigned*)&hp;
        *(unsigned*)(smem + SM_YL + r * 272 + kp * 4) = *(unsigned*)&lp;
        *(float2*)&yres[r * 132 + 2 * kp] = y2;
    }
    copy_w(smem, tid, g_WinH[depth], g_WinL[depth]);
    __syncthreads();

    const int rA = r0 + (lane >> 2);
    const int colBase = n0w + (lane & 3) * 2;

    // ---- GEMM1 half 0: a = Y @ Win[0:128]^T + b_in ----
    {
        float acc[8][4];
#pragma unroll
        for (int q = 0; q < 8; ++q)
#pragma unroll
            for (int j = 0; j < 4; ++j) acc[q][j] = 0.f;
        do_gemm(smem, sb, SM_YH, SM_YL, r0, n0w, lane, acc);
#pragma unroll
        for (int q = 0; q < 8; ++q) {
            int col = colBase + q * 8;
            float bb0 = __ldg(&b_in[col]), bb1 = __ldg(&b_in[col + 1]);
            float2 v0 = make_float2(acc[q][0] + bb0, acc[q][1] + bb1);
            float2 v1 = make_float2(acc[q][2] + bb0, acc[q][3] + bb1);
            *(float2*)&zbuf[rA * 132 + col]       = v0;
            *(float2*)&zbuf[(rA + 8) * 132 + col] = v1;
        }
    }
    __syncthreads();
    copy_w(smem, tid, g_WinH[depth] + 128 * 128, g_WinL[depth] + 128 * 128);
    __syncthreads();

    // ---- GEMM1 half 1: g; u = a * sigmoid(g) -> U hi/lo tiles ----
    {
        float acc[8][4];
#pragma unroll
        for (int q = 0; q < 8; ++q)
#pragma unroll
            for (int j = 0; j < 4; ++j) acc[q][j] = 0.f;
        do_gemm(smem, sb, SM_YH, SM_YL, r0, n0w, lane, acc);
#pragma unroll
        for (int q = 0; q < 8; ++q) {
            int col = colBase + q * 8;
            float bb0 = __ldg(&b_in[128 + col]), bb1 = __ldg(&b_in[128 + col + 1]);
            float2 a0 = *(const float2*)&zbuf[rA * 132 + col];
            float2 a1 = *(const float2*)&zbuf[(rA + 8) * 132 + col];
            float u00 = a0.x / (1.0f + expf(-(acc[q][0] + bb0)));
            float u01 = a0.y / (1.0f + expf(-(acc[q][1] + bb1)));
            float u10 = a1.x / (1.0f + expf(-(acc[q][2] + bb0)));
            float u11 = a1.y / (1.0f + expf(-(acc[q][3] + bb1)));
#pragma unroll
            for (int rr = 0; rr < 2; ++rr) {
                float u0 = rr ? u10 : u00, u1 = rr ? u11 : u01;
                __nv_bfloat16 h0 = __float2bfloat16(u0), h1 = __float2bfloat16(u1);
                __nv_bfloat16 l0 = __float2bfloat16(u0 - __bfloat162float(h0));
                __nv_bfloat16 l1 = __float2bfloat16(u1 - __bfloat162float(h1));
                __nv_bfloat162 hp = __halves2bfloat162(h0, h1);
                __nv_bfloat162 lp = __halves2bfloat162(l0, l1);
                int r = rA + rr * 8;
                *(unsigned*)(smem + SM_UH + r * 272 + col * 2) = *(unsigned*)&hp;
                *(unsigned*)(smem + SM_UL + r * 272 + col * 2) = *(unsigned*)&lp;
            }
        }
    }
    __syncthreads();
    copy_w(smem, tid, g_WoutH[depth], g_WoutL[depth]);
    __syncthreads();

    // ---- GEMM2: z = U @ Wout^T + b_out + y -> zbuf ----
    {
        float acc[8][4];
#pragma unroll
        for (int q = 0; q < 8; ++q)
#pragma unroll
            for (int j = 0; j < 4; ++j) acc[q][j] = 0.f;
        do_gemm(smem, sb, SM_UH, SM_UL, r0, n0w, lane, acc);
#pragma unroll
        for (int q = 0; q < 8; ++q) {
            int col = colBase + q * 8;
            float bb0 = __ldg(&b_out[col]), bb1 = __ldg(&b_out[col + 1]);
            float2 y0 = *(const float2*)&yres[rA * 132 + col];
            float2 y1 = *(const float2*)&yres[(rA + 8) * 132 + col];
            float2 v0 = make_float2(acc[q][0] + bb0 + y0.x, acc[q][1] + bb1 + y0.y);
            float2 v1 = make_float2(acc[q][2] + bb0 + y1.x, acc[q][3] + bb1 + y1.y);
            *(float2*)&zbuf[rA * 132 + col]       = v0;
            *(float2*)&zbuf[(rA + 8) * 132 + col] = v1;
        }
    }
    __syncthreads();

    // ---- LayerNorm per row over 128 channels -> g_bufA ----
    for (int r = wid; r < 64; r += 8) {
        float v[4]; float s = 0.f;
#pragma unroll
        for (int i = 0; i < 4; ++i) {
            v[i] = zbuf[r * 132 + lane + i * 32];
            s += v[i];
        }
#pragma unroll
        for (int off = 16; off; off >>= 1) s += __shfl_xor_sync(0xffffffffu, s, off);
        float mu = s * (1.0f / 128.0f);
        float vs = 0.f;
#pragma unroll
        for (int i = 0; i < 4; ++i) { float d = v[i] - mu; vs += d * d; }
#pragma unroll
        for (int off = 16; off; off >>= 1) vs += __shfl_xor_sync(0xffffffffu, vs, off);
        float rstd = rsqrtf(vs * (1.0f / 128.0f) + 1e-5f);
#pragma unroll
        for (int i = 0; i < 4; ++i) {
            int ch = lane + i * 32;
            g_bufA[(row0 + r) * CD + ch] =
                (v[i] - mu) * rstd * __ldg(&gamma[ch]) + __ldg(&beta[ch]);
        }
    }
}

// ---------------- final mean over L ----------------
__global__ __launch_bounds__(512) void mean_kernel(float* __restrict__ out) {
    __shared__ float part[4][128];
    const int b  = blockIdx.x;
    const int c  = threadIdx.x & 127;
    const int lq = threadIdx.x >> 7;
    const float* p = g_bufA + (size_t)b * SEQ * CD + c;
    float s = 0.f;
    for (int l = lq * 128; l < lq * 128 + 128; ++l) s += p[l * CD];
    part[lq][c] = s;
    __syncthreads();
    if (lq == 0)
        out[b * CD + c] = (part[0][c] + part[1][c] + part[2][c] + part[3][c]) * (1.0f / 512.0f);
}

extern "C" void kernel_launch(void* const* d_in, const int* in_sizes, int n_in,
                              void* d_out, int out_size) {
    const float* x     = (const float*)d_in[0];
    const float* Wp    = (const float*)d_in[2];
    const float* bp    = (const float*)d_in[3];
    const float* ltau  = (const float*)d_in[4];
    const float* W_in  = (const float*)d_in[5];
    const float* b_in  = (const float*)d_in[6];
    const float* W_out = (const float*)d_in[7];
    const float* b_out = (const float*)d_in[8];
    const float* gamma = (const float*)d_in[9];
    const float* beta  = (const float*)d_in[10];
    float* out = (float*)d_out;

    cudaFuncSetAttribute(mlp_mma_kernel, cudaFuncAttributeMaxDynamicSharedMemorySize,
                         MMA_SMEM_BYTES);

    stage_w_kernel<<<3, 256>>>(W_in, W_out);
    proj_kernel<<<NTOK / 32, 128>>>(x, Wp, bp);
    for (int d = 0; d < 3; ++d) {
        conv_kernel<<<NGR * 4, 128>>>(ltau + d * 128);
        mlp_mma_kernel<<<NTOK / 64, 256, MMA_SMEM_BYTES>>>(
            d, b_in + d * 256, b_out + d * 128, gamma + d * 128, beta + d * 128);
    }
    mean_kernel<<<NGR, 512>>>(out);
}

// round 7
// speedup vs baseline: 2.2302x; 1.0324x over previous
#include <cuda_runtime.h>
#include <cuda_bf16.h>
#include <cstdint>

#define NTOK 65536
#define CD   128
#define SEQ  512
#define NGR  128

__device__ float g_bufA[(size_t)NTOK * CD];
__device__ float g_bufB[(size_t)NTOK * CD];

// bf16 hi/lo weight images (row-major [n][k], k=128)
__device__ __nv_bfloat16 g_WinH[3][256 * 128];
__device__ __nv_bfloat16 g_WinL[3][256 * 128];
__device__ __nv_bfloat16 g_WoutH[3][128 * 128];
__device__ __nv_bfloat16 g_WoutL[3][128 * 128];

__device__ __forceinline__ unsigned int smem_u32(const void* p) {
    unsigned int a;
    asm("{ .reg .u64 t; cvta.to.shared.u64 t, %1; cvt.u32.u64 %0, t; }" : "=r"(a) : "l"(p));
    return a;
}

#define LDSM4(v, addr) \
    asm volatile("ldmatrix.sync.aligned.m8n8.x4.shared.b16 {%0,%1,%2,%3}, [%4];" \
                 : "=r"((v).x), "=r"((v).y), "=r"((v).z), "=r"((v).w) : "r"(addr))

#define MMA_BF16(d, a, b0, b1) \
    asm volatile("mma.sync.aligned.m16n8k16.row.col.f32.bf16.bf16.f32 " \
                 "{%0,%1,%2,%3}, {%4,%5,%6,%7}, {%8,%9}, {%0,%1,%2,%3};" \
                 : "+f"((d)[0]), "+f"((d)[1]), "+f"((d)[2]), "+f"((d)[3]) \
                 : "r"((a).x), "r"((a).y), "r"((a).z), "r"((a).w), "r"(b0), "r"(b1))

// ---------------- weight staging: fp32 -> bf16 hi/lo ----------------
__global__ __launch_bounds__(256) void stage_w_kernel(const float* __restrict__ W_in,
                                                      const float* __restrict__ W_out) {
    const int d = blockIdx.x;
    const int tid = threadIdx.x;
    for (int i = tid; i < 256 * 128; i += 256) {
        float v = W_in[d * 256 * 128 + i];
        __nv_bfloat16 h = __float2bfloat16(v);
        g_WinH[d][i] = h;
        g_WinL[d][i] = __float2bfloat16(v - __bfloat162float(h));
    }
    for (int i = tid; i < 128 * 128; i += 256) {
        float v = W_out[d * 128 * 128 + i];
        __nv_bfloat16 h = __float2bfloat16(v);
        g_WoutH[d][i] = h;
        g_WoutL[d][i] = __float2bfloat16(v - __bfloat162float(h));
    }
}

// ---------------- projection (FFMA2) ----------------
__device__ __forceinline__ void ffma2(unsigned long long& d,
                                      unsigned long long a,
                                      unsigned long long b) {
    asm("fma.rn.f32x2 %0, %1, %2, %0;" : "+l"(d) : "l"(a), "l"(b));
}
__device__ __forceinline__ unsigned long long rep2(float v) {
    unsigned long long r;
    unsigned int u = __float_as_uint(v);
    asm("mov.b64 %0, {%1, %1};" : "=l"(r) : "r"(u));
    return r;
}
__global__ __launch_bounds__(128) void proj_kernel(const float* __restrict__ x,
                                                   const float* __restrict__ Wp,
                                                   const float* __restrict__ bproj) {
    __shared__ float xs2[64 * 36];
    __shared__ float WT[64 * 132];
    const int tid = threadIdx.x;
    const size_t row0 = (size_t)blockIdx.x * 32;

    for (int i = tid; i < 32 * 64; i += 128) {
        int r = i >> 6, k = i & 63;
        xs2[k * 36 + r] = x[(row0 + (size_t)r) * 64 + k];
    }
    for (int i = tid; i < 128 * 64; i += 128) {
        int j = i >> 6, k = i & 63;
        WT[k * 132 + j] = Wp[i];
    }
    __syncthreads();

    const int cg = tid & 31, rg = tid >> 5;
    const int j0 = cg * 4, r0 = rg * 8;
    unsigned long long acc[4][4];
#pragma unroll
    for (int i = 0; i < 4; ++i)
#pragma unroll
        for (int j = 0; j < 4; ++j) acc[i][j] = 0ull;

#pragma unroll 8
    for (int k = 0; k < 64; ++k) {
        ulonglong2 a0 = *(const ulonglong2*)&xs2[k * 36 + r0];
        ulonglong2 a1 = *(const ulonglong2*)&xs2[k * 36 + r0 + 4];
        float4 b = *(const float4*)&WT[k * 132 + j0];
        unsigned long long ap[4] = {a0.x, a0.y, a1.x, a1.y};
        unsigned long long bp4[4] = {rep2(b.x), rep2(b.y), rep2(b.z), rep2(b.w)};
#pragma unroll
        for (int ip = 0; ip < 4; ++ip)
#pragma unroll
            for (int j = 0; j < 4; ++j)
                ffma2(acc[ip][j], ap[ip], bp4[j]);
    }
#pragma unroll
    for (int j = 0; j < 4; ++j) {
        float bj = bproj[j0 + j];
#pragma unroll
        for (int ip = 0; ip < 4; ++ip) {
            float2 f = *(float2*)&acc[ip][j];
            g_bufA[(row0 + r0 + 2 * ip) * CD + j0 + j]     = f.x + bj;
            g_bufA[(row0 + r0 + 2 * ip + 1) * CD + j0 + j] = f.y + bj;
        }
    }
}

// ---------------- conv: 8 chunks of 64 for more parallelism ----------------
__global__ __launch_bounds__(128) void conv_kernel(const float* __restrict__ log_tau_d) {
    const int b = blockIdx.x >> 3;
    const int q = blockIdx.x & 7;
    const int c = threadIdx.x;

    float tau  = fmaxf(expf(log_tau_d[c]), 0.001f);
    float it   = 1.0f / tau;
    float rho  = expf(-it);
    float rhoK = expf(-256.0f * it);
    float den  = 1.0f - rho;
    float S    = (den > 1e-20f) ? (1.0f - rhoK) / den : 256.0f;
    float scale = 1.0f / (S + 1e-8f);

    const float* xp = g_bufA + (size_t)b * SEQ * CD + c;
    float*       yp = g_bufB + (size_t)b * SEQ * CD + c;

    const int l_top = q * 64 + 63;
    const int base  = l_top - 255;
    float acc = 0.f;
#pragma unroll 8
    for (int j = 255; j >= 0; --j) {
        int idx = base + j;
        float xv = (idx >= 0) ? xp[idx * CD] : 0.f;
        acc = fmaf(rho, acc, xv);
    }
    int l = l_top;
#pragma unroll 8
    for (int n = 0; n < 64; ++n, --l) {
        yp[l * CD] = acc * scale;
        float xold = (l >= 256) ? xp[(l - 256) * CD] : 0.f;
        float xtop = xp[l * CD];
        acc = fmaf(rho, acc, fmaf(-rhoK, xtop, xold));
    }
}

// ---------------- mma.sync fused MLP (single-pass GEMM1, GLU in regs) ----------------
// rows padded to 272 B (136 halves)
#define SM_YH   0
#define SM_YL   17408
#define SM_WH   34816
#define SM_WL   104448          /* 34816 + 256*272 */
#define SM_UH   174080          /* 104448 + 256*272 */
#define SM_UL   191488
#define SM_ZB   SM_UH           /* fp32 z overlays U after GEMM2 */
#define MMA_SMEM_BYTES 208896

__device__ __forceinline__ void copy_w(char* smem, int tid, int rows,
                                       const __nv_bfloat16* __restrict__ srcH,
                                       const __nv_bfloat16* __restrict__ srcL) {
    const int n = rows * 16;              // uint4 per image
    for (int i = tid; i < n; i += 256) {
        int r = i >> 4, c = i & 15;
        *(uint4*)(smem + SM_WH + r * 272 + c * 16) = ((const uint4*)srcH)[i];
        *(uint4*)(smem + SM_WL + r * 272 + c * 16) = ((const uint4*)srcL)[i];
    }
}

__global__ __launch_bounds__(256) void mlp_mma_kernel(int depth,
                                                      const float* __restrict__ b_in,
                                                      const float* __restrict__ b_out,
                                                      const float* __restrict__ gamma,
                                                      const float* __restrict__ beta) {
    extern __shared__ char smem[];
    const unsigned sb = smem_u32(smem);
    const int tid = threadIdx.x;
    const int wid = tid >> 5, lane = tid & 31;
    const int wr = wid >> 2;              // 0..1: row group (m32)
    const int wc = wid & 3;               // 0..3: col group (n32)
    const int r0 = wr * 32;
    const int n0 = wc * 32;
    const size_t row0 = (size_t)blockIdx.x * 64;

    // ---- load Y tile -> bf16 hi/lo tiles; stage full W_in (256 rows hi/lo) ----
#pragma unroll
    for (int t = 0; t < 16; ++t) {
        int idx = tid + t * 256;          // pair index over 64 x 64
        int r = idx >> 6, kp = idx & 63;
        float2 y2 = *(const float2*)&g_bufB[(row0 + r) * CD + 2 * kp];
        __nv_bfloat16 h0 = __float2bfloat16(y2.x), h1 = __float2bfloat16(y2.y);
        __nv_bfloat16 l0 = __float2bfloat16(y2.x - __bfloat162float(h0));
        __nv_bfloat16 l1 = __float2bfloat16(y2.y - __bfloat162float(h1));
        __nv_bfloat162 hp = __halves2bfloat162(h0, h1);
        __nv_bfloat162 lp = __halves2bfloat162(l0, l1);
        *(unsigned*)(smem + SM_YH + r * 272 + kp * 4) = *(unsigned*)&hp;
        *(unsigned*)(smem + SM_YL + r * 272 + kp * 4) = *(unsigned*)&lp;
    }
    copy_w(smem, tid, 256, g_WinH[depth], g_WinL[depth]);
    __syncthreads();

    const int rA = (lane >> 2);           // 0..7 within m16 tile
    const int cB = (lane & 3) * 2;        // col pair base within n8
    const unsigned browb = (unsigned)((lane & 7) + ((lane & 16) >> 1));
    const unsigned bcolb = (unsigned)(lane & 8);

    // ---- GEMM1: a (cols n0..) and g (cols 128+n0..) in one pass ----
    float acc[2][2][4][4];                // [target][mtile][n8][4]
#pragma unroll
    for (int t = 0; t < 2; ++t)
#pragma unroll
        for (int m = 0; m < 2; ++m)
#pragma unroll
            for (int n = 0; n < 4; ++n)
#pragma unroll
                for (int j = 0; j < 4; ++j) acc[t][m][n][j] = 0.f;

#pragma unroll
    for (int ks = 0; ks < 8; ++ks) {
        const int k0 = ks * 16;
        unsigned aoff = (unsigned)(r0 + (lane & 15)) * 272u
                      + (unsigned)(k0 + ((lane & 16) >> 1)) * 2u;
        uint4 ah0, ah1, al0, al1;
        LDSM4(ah0, sb + SM_YH + aoff);
        LDSM4(ah1, sb + SM_YH + aoff + 16 * 272);
        LDSM4(al0, sb + SM_YL + aoff);
        LDSM4(al1, sb + SM_YL + aoff + 16 * 272);
#pragma unroll
        for (int t = 0; t < 2; ++t) {
            const int nbase = t * 128 + n0;
#pragma unroll
            for (int nb = 0; nb < 2; ++nb) {
                unsigned boff = (unsigned)(nbase + nb * 16 + browb) * 272u
                              + (bcolb + (unsigned)k0) * 2u;
                uint4 bh, bl;
                LDSM4(bh, sb + SM_WH + boff);
                LDSM4(bl, sb + SM_WL + boff);
                float* c00 = acc[t][0][nb * 2];
                float* c01 = acc[t][0][nb * 2 + 1];
                float* c10 = acc[t][1][nb * 2];
                float* c11 = acc[t][1][nb * 2 + 1];
                MMA_BF16(c00, ah0, bh.x, bh.y);
                MMA_BF16(c00, ah0, bl.x, bl.y);
                MMA_BF16(c00, al0, bh.x, bh.y);
                MMA_BF16(c01, ah0, bh.z, bh.w);
                MMA_BF16(c01, ah0, bl.z, bl.w);
                MMA_BF16(c01, al0, bh.z, bh.w);
                MMA_BF16(c10, ah1, bh.x, bh.y);
                MMA_BF16(c10, ah1, bl.x, bl.y);
                MMA_BF16(c10, al1, bh.x, bh.y);
                MMA_BF16(c11, ah1, bh.z, bh.w);
                MMA_BF16(c11, ah1, bl.z, bl.w);
                MMA_BF16(c11, al1, bh.z, bh.w);
            }
        }
    }

    // ---- GLU in registers -> U hi/lo tiles ----
#pragma unroll
    for (int m = 0; m < 2; ++m) {
#pragma unroll
        for (int n = 0; n < 4; ++n) {
            const int col = n0 + n * 8 + cB;
            const float ba0 = __ldg(&b_in[col]),       ba1 = __ldg(&b_in[col + 1]);
            const float bg0 = __ldg(&b_in[128 + col]), bg1 = __ldg(&b_in[128 + col + 1]);
#pragma unroll
            for (int rr = 0; rr < 2; ++rr) {
                const int r = r0 + m * 16 + rA + rr * 8;
                float av0 = acc[0][m][n][rr * 2]     + ba0;
                float av1 = acc[0][m][n][rr * 2 + 1] + ba1;
                float gv0 = acc[1][m][n][rr * 2]     + bg0;
                float gv1 = acc[1][m][n][rr * 2 + 1] + bg1;
                float u0 = av0 / (1.0f + expf(-gv0));
                float u1 = av1 / (1.0f + expf(-gv1));
                __nv_bfloat16 h0 = __float2bfloat16(u0), h1 = __float2bfloat16(u1);
                __nv_bfloat16 l0 = __float2bfloat16(u0 - __bfloat162float(h0));
                __nv_bfloat16 l1 = __float2bfloat16(u1 - __bfloat162float(h1));
                __nv_bfloat162 hp = __halves2bfloat162(h0, h1);
                __nv_bfloat162 lp = __halves2bfloat162(l0, l1);
                *(unsigned*)(smem + SM_UH + r * 272 + col * 2) = *(unsigned*)&hp;
                *(unsigned*)(smem + SM_UL + r * 272 + col * 2) = *(unsigned*)&lp;
            }
        }
    }
    __syncthreads();

    // ---- stage W_out over W region rows 0-127 ----
    copy_w(smem, tid, 128, g_WoutH[depth], g_WoutL[depth]);
    __syncthreads();

    // ---- GEMM2: z-acc = U @ Wout^T ----
    float acc2[2][4][4];
#pragma unroll
    for (int m = 0; m < 2; ++m)
#pragma unroll
        for (int n = 0; n < 4; ++n)
#pragma unroll
            for (int j = 0; j < 4; ++j) acc2[m][n][j] = 0.f;

#pragma unroll
    for (int ks = 0; ks < 8; ++ks) {
        const int k0 = ks * 16;
        unsigned aoff = (unsigned)(r0 + (lane & 15)) * 272u
                      + (unsigned)(k0 + ((lane & 16) >> 1)) * 2u;
        uint4 ah0, ah1, al0, al1;
        LDSM4(ah0, sb + SM_UH + aoff);
        LDSM4(ah1, sb + SM_UH + aoff + 16 * 272);
        LDSM4(al0, sb + SM_UL + aoff);
        LDSM4(al1, sb + SM_UL + aoff + 16 * 272);
#pragma unroll
        for (int nb = 0; nb < 2; ++nb) {
            unsigned boff = (unsigned)(n0 + nb * 16 + browb) * 272u
                          + (bcolb + (unsigned)k0) * 2u;
            uint4 bh, bl;
            LDSM4(bh, sb + SM_WH + boff);
            LDSM4(bl, sb + SM_WL + boff);
            float* c00 = acc2[0][nb * 2];
            float* c01 = acc2[0][nb * 2 + 1];
            float* c10 = acc2[1][nb * 2];
            float* c11 = acc2[1][nb * 2 + 1];
            MMA_BF16(c00, ah0, bh.x, bh.y);
            MMA_BF16(c00, ah0, bl.x, bl.y);
            MMA_BF16(c00, al0, bh.x, bh.y);
            MMA_BF16(c01, ah0, bh.z, bh.w);
            MMA_BF16(c01, ah0, bl.z, bl.w);
            MMA_BF16(c01, al0, bh.z, bh.w);
            MMA_BF16(c10, ah1, bh.x, bh.y);
            MMA_BF16(c10, ah1, bl.x, bl.y);
            MMA_BF16(c10, al1, bh.x, bh.y);
            MMA_BF16(c11, ah1, bh.z, bh.w);
            MMA_BF16(c11, ah1, bl.z, bl.w);
            MMA_BF16(c11, al1, bh.z, bh.w);
        }
    }
    __syncthreads();   // all U reads done; safe to overlay z

    // ---- epilogue: z = acc2 + b_out + y(recon) -> zbuf (overlays U) ----
    float* zbuf = (float*)(smem + SM_ZB);  // [r][132]
#pragma unroll
    for (int m = 0; m < 2; ++m) {
#pragma unroll
        for (int n = 0; n < 4; ++n) {
            const int col = n0 + n * 8 + cB;
            const float bb0 = __ldg(&b_out[col]), bb1 = __ldg(&b_out[col + 1]);
#pragma unroll
            for (int rr = 0; rr < 2; ++rr) {
                const int r = r0 + m * 16 + rA + rr * 8;
                __nv_bfloat162 hp = *(__nv_bfloat162*)(smem + SM_YH + r * 272 + col * 2);
                __nv_bfloat162 lp = *(__nv_bfloat162*)(smem + SM_YL + r * 272 + col * 2);
                float y0 = __bfloat162float(hp.x) + __bfloat162float(lp.x);
                float y1 = __bfloat162float(hp.y) + __bfloat162float(lp.y);
                float z0 = acc2[m][n][rr * 2]     + bb0 + y0;
                float z1 = acc2[m][n][rr * 2 + 1] + bb1 + y1;
                zbuf[r * 132 + col]     = z0;
                zbuf[r * 132 + col + 1] = z1;
            }
        }
    }
    __syncthreads();

    // ---- LayerNorm per row over 128 channels -> g_bufA ----
    for (int r = wid; r < 64; r += 8) {
        float v[4]; float s = 0.f;
#pragma unroll
        for (int i = 0; i < 4; ++i) {
            v[i] = zbuf[r * 132 + lane + i * 32];
            s += v[i];
        }
#pragma unroll
        for (int off = 16; off; off >>= 1) s += __shfl_xor_sync(0xffffffffu, s, off);
        float mu = s * (1.0f / 128.0f);
        float vs = 0.f;
#pragma unroll
        for (int i = 0; i < 4; ++i) { float d = v[i] - mu; vs += d * d; }
#pragma unroll
        for (int off = 16; off; off >>= 1) vs += __shfl_xor_sync(0xffffffffu, vs, off);
        float rstd = rsqrtf(vs * (1.0f / 128.0f) + 1e-5f);
#pragma unroll
        for (int i = 0; i < 4; ++i) {
            int ch = lane + i * 32;
            g_bufA[(row0 + r) * CD + ch] =
                (v[i] - mu) * rstd * __ldg(&gamma[ch]) + __ldg(&beta[ch]);
        }
    }
}

// ---------------- final mean over L ----------------
__global__ __launch_bounds__(512) void mean_kernel(float* __restrict__ out) {
    __shared__ float part[4][128];
    const int b  = blockIdx.x;
    const int c  = threadIdx.x & 127;
    const int lq = threadIdx.x >> 7;
    const float* p = g_bufA + (size_t)b * SEQ * CD + c;
    float s = 0.f;
    for (int l = lq * 128; l < lq * 128 + 128; ++l) s += p[l * CD];
    part[lq][c] = s;
    __syncthreads();
    if (lq == 0)
        out[b * CD + c] = (part[0][c] + part[1][c] + part[2][c] + part[3][c]) * (1.0f / 512.0f);
}

extern "C" void kernel_launch(void* const* d_in, const int* in_sizes, int n_in,
                              void* d_out, int out_size) {
    const float* x     = (const float*)d_in[0];
    const float* Wp    = (const float*)d_in[2];
    const float* bp    = (const float*)d_in[3];
    const float* ltau  = (const float*)d_in[4];
    const float* W_in  = (const float*)d_in[5];
    const float* b_in  = (const float*)d_in[6];
    const float* W_out = (const float*)d_in[7];
    const float* b_out = (const float*)d_in[8];
    const float* gamma = (const float*)d_in[9];
    const float* beta  = (const float*)d_in[10];
    float* out = (float*)d_out;

    cudaFuncSetAttribute(mlp_mma_kernel, cudaFuncAttributeMaxDynamicSharedMemorySize,
                         MMA_SMEM_BYTES);

    stage_w_kernel<<<3, 256>>>(W_in, W_out);
    proj_kernel<<<NTOK / 32, 128>>>(x, Wp, bp);
    for (int d = 0; d < 3; ++d) {
        conv_kernel<<<NGR * 8, 128>>>(ltau + d * 128);
        mlp_mma_kernel<<<NTOK / 64, 256, MMA_SMEM_BYTES>>>(
            d, b_in + d * 256, b_out + d * 128, gamma + d * 128, beta + d * 128);
    }
    mean_kernel<<<NGR, 512>>>(out);
}

// round 8
// speedup vs baseline: 2.9654x; 1.3296x over previous
#include <cuda_runtime.h>
#include <cuda_bf16.h>
#include <cstdint>

#define NTOK 65536
#define CD   128
#define SEQ  512
#define NGR  128

__device__ float g_bufA[(size_t)NTOK * CD];
__device__ float g_bufB[(size_t)NTOK * CD];

// bf16 hi/lo weight images (row-major [n][k], k=128)
__device__ __nv_bfloat16 g_WinH[3][256 * 128];
__device__ __nv_bfloat16 g_WinL[3][256 * 128];
__device__ __nv_bfloat16 g_WoutH[3][128 * 128];
__device__ __nv_bfloat16 g_WoutL[3][128 * 128];

__device__ __forceinline__ unsigned int smem_u32(const void* p) {
    unsigned int a;
    asm("{ .reg .u64 t; cvta.to.shared.u64 t, %1; cvt.u32.u64 %0, t; }" : "=r"(a) : "l"(p));
    return a;
}

#define LDSM4(v, addr) \
    asm volatile("ldmatrix.sync.aligned.m8n8.x4.shared.b16 {%0,%1,%2,%3}, [%4];" \
                 : "=r"((v).x), "=r"((v).y), "=r"((v).z), "=r"((v).w) : "r"(addr))

#define MMA_BF16(d, a, b0, b1) \
    asm volatile("mma.sync.aligned.m16n8k16.row.col.f32.bf16.bf16.f32 " \
                 "{%0,%1,%2,%3}, {%4,%5,%6,%7}, {%8,%9}, {%0,%1,%2,%3};" \
                 : "+f"((d)[0]), "+f"((d)[1]), "+f"((d)[2]), "+f"((d)[3]) \
                 : "r"((a).x), "r"((a).y), "r"((a).z), "r"((a).w), "r"(b0), "r"(b1))

// ---------------- weight staging: fp32 -> bf16 hi/lo ----------------
__global__ __launch_bounds__(256) void stage_w_kernel(const float* __restrict__ W_in,
                                                      const float* __restrict__ W_out) {
    const int d = blockIdx.x;
    const int tid = threadIdx.x;
    for (int i = tid; i < 256 * 128; i += 256) {
        float v = W_in[d * 256 * 128 + i];
        __nv_bfloat16 h = __float2bfloat16(v);
        g_WinH[d][i] = h;
        g_WinL[d][i] = __float2bfloat16(v - __bfloat162float(h));
    }
    for (int i = tid; i < 128 * 128; i += 256) {
        float v = W_out[d * 128 * 128 + i];
        __nv_bfloat16 h = __float2bfloat16(v);
        g_WoutH[d][i] = h;
        g_WoutL[d][i] = __float2bfloat16(v - __bfloat162float(h));
    }
}

// ---------------- projection (FFMA2) ----------------
__device__ __forceinline__ void ffma2(unsigned long long& d,
                                      unsigned long long a,
                                      unsigned long long b) {
    asm("fma.rn.f32x2 %0, %1, %2, %0;" : "+l"(d) : "l"(a), "l"(b));
}
__device__ __forceinline__ unsigned long long rep2(float v) {
    unsigned long long r;
    unsigned int u = __float_as_uint(v);
    asm("mov.b64 %0, {%1, %1};" : "=l"(r) : "r"(u));
    return r;
}
__global__ __launch_bounds__(128) void proj_kernel(const float* __restrict__ x,
                                                   const float* __restrict__ Wp,
                                                   const float* __restrict__ bproj) {
    __shared__ float xs2[64 * 36];
    __shared__ float WT[64 * 132];
    const int tid = threadIdx.x;
    const size_t row0 = (size_t)blockIdx.x * 32;

    for (int i = tid; i < 32 * 64; i += 128) {
        int r = i >> 6, k = i & 63;
        xs2[k * 36 + r] = x[(row0 + (size_t)r) * 64 + k];
    }
    for (int i = tid; i < 128 * 64; i += 128) {
        int j = i >> 6, k = i & 63;
        WT[k * 132 + j] = Wp[i];
    }
    __syncthreads();

    const int cg = tid & 31, rg = tid >> 5;
    const int j0 = cg * 4, r0 = rg * 8;
    unsigned long long acc[4][4];
#pragma unroll
    for (int i = 0; i < 4; ++i)
#pragma unroll
        for (int j = 0; j < 4; ++j) acc[i][j] = 0ull;

#pragma unroll 8
    for (int k = 0; k < 64; ++k) {
        ulonglong2 a0 = *(const ulonglong2*)&xs2[k * 36 + r0];
        ulonglong2 a1 = *(const ulonglong2*)&xs2[k * 36 + r0 + 4];
        float4 b = *(const float4*)&WT[k * 132 + j0];
        unsigned long long ap[4] = {a0.x, a0.y, a1.x, a1.y};
        unsigned long long bp4[4] = {rep2(b.x), rep2(b.y), rep2(b.z), rep2(b.w)};
#pragma unroll
        for (int ip = 0; ip < 4; ++ip)
#pragma unroll
            for (int j = 0; j < 4; ++j)
                ffma2(acc[ip][j], ap[ip], bp4[j]);
    }
#pragma unroll
    for (int j = 0; j < 4; ++j) {
        float bj = bproj[j0 + j];
#pragma unroll
        for (int ip = 0; ip < 4; ++ip) {
            float2 f = *(float2*)&acc[ip][j];
            g_bufA[(row0 + r0 + 2 * ip) * CD + j0 + j]     = f.x + bj;
            g_bufA[(row0 + r0 + 2 * ip + 1) * CD + j0 + j] = f.y + bj;
        }
    }
}

// ---------------- conv: 8 chunks of 64 ----------------
__global__ __launch_bounds__(128) void conv_kernel(const float* __restrict__ log_tau_d) {
    const int b = blockIdx.x >> 3;
    const int q = blockIdx.x & 7;
    const int c = threadIdx.x;

    float tau  = fmaxf(expf(log_tau_d[c]), 0.001f);
    float it   = 1.0f / tau;
    float rho  = expf(-it);
    float rhoK = expf(-256.0f * it);
    float den  = 1.0f - rho;
    float S    = (den > 1e-20f) ? (1.0f - rhoK) / den : 256.0f;
    float scale = 1.0f / (S + 1e-8f);

    const float* xp = g_bufA + (size_t)b * SEQ * CD + c;
    float*       yp = g_bufB + (size_t)b * SEQ * CD + c;

    const int l_top = q * 64 + 63;
    const int base  = l_top - 255;
    float acc = 0.f;
#pragma unroll 8
    for (int j = 255; j >= 0; --j) {
        int idx = base + j;
        float xv = (idx >= 0) ? xp[idx * CD] : 0.f;
        acc = fmaf(rho, acc, xv);
    }
    int l = l_top;
#pragma unroll 8
    for (int n = 0; n < 64; ++n, --l) {
        yp[l * CD] = acc * scale;
        float xold = (l >= 256) ? xp[(l - 256) * CD] : 0.f;
        float xtop = xp[l * CD];
        acc = fmaf(rho, acc, fmaf(-rhoK, xtop, xold));
    }
}

// ---------------- mma.sync fused MLP: 102KB smem -> 2 CTAs/SM ----------------
// rows padded to 272 B (136 halves)
#define SM_YH   0
#define SM_YL   17408
#define SM_WH   34816
#define SM_WL   69632
#define SM_UH   SM_YH           /* U overwrites Y after GEMM1 */
#define SM_UL   SM_YL
#define SM_ZB   SM_YH           /* fp32 z overlays U after GEMM2 */
#define MMA_SMEM_BYTES 104448

__device__ __forceinline__ void copy_w(char* smem, int tid,
                                       const __nv_bfloat16* __restrict__ srcH,
                                       const __nv_bfloat16* __restrict__ srcL) {
#pragma unroll
    for (int t = 0; t < 8; ++t) {
        int i = tid + t * 256;            // uint4 index over 128 rows x 16 chunks
        int r = i >> 4, c = i & 15;
        *(uint4*)(smem + SM_WH + r * 272 + c * 16) = ((const uint4*)srcH)[i];
        *(uint4*)(smem + SM_WL + r * 272 + c * 16) = ((const uint4*)srcL)[i];
    }
}

// one GEMM pass: A tiles (m32 at row r0) x staged W (n32 at col n0) -> acc[2][4][4]
__device__ __forceinline__ void gemm_pass(char* smem, unsigned sb, unsigned aBaseH,
                                          unsigned aBaseL, int r0, int n0, int lane,
                                          float acc[2][4][4]) {
    const unsigned browb = (unsigned)((lane & 7) + ((lane & 16) >> 1));
    const unsigned bcolb = (unsigned)(lane & 8);
#pragma unroll
    for (int ks = 0; ks < 8; ++ks) {
        const int k0 = ks * 16;
        unsigned aoff = (unsigned)(r0 + (lane & 15)) * 272u
                      + (unsigned)(k0 + ((lane & 16) >> 1)) * 2u;
        uint4 ah0, ah1, al0, al1;
        LDSM4(ah0, sb + aBaseH + aoff);
        LDSM4(ah1, sb + aBaseH + aoff + 16 * 272);
        LDSM4(al0, sb + aBaseL + aoff);
        LDSM4(al1, sb + aBaseL + aoff + 16 * 272);
#pragma unroll
        for (int nb = 0; nb < 2; ++nb) {
            unsigned boff = (unsigned)(n0 + nb * 16 + browb) * 272u
                          + (bcolb + (unsigned)k0) * 2u;
            uint4 bh, bl;
            LDSM4(bh, sb + SM_WH + boff);
            LDSM4(bl, sb + SM_WL + boff);
            float* c00 = acc[0][nb * 2];
            float* c01 = acc[0][nb * 2 + 1];
            float* c10 = acc[1][nb * 2];
            float* c11 = acc[1][nb * 2 + 1];
            MMA_BF16(c00, ah0, bh.x, bh.y);
            MMA_BF16(c00, ah0, bl.x, bl.y);
            MMA_BF16(c00, al0, bh.x, bh.y);
            MMA_BF16(c01, ah0, bh.z, bh.w);
            MMA_BF16(c01, ah0, bl.z, bl.w);
            MMA_BF16(c01, al0, bh.z, bh.w);
            MMA_BF16(c10, ah1, bh.x, bh.y);
            MMA_BF16(c10, ah1, bl.x, bl.y);
            MMA_BF16(c10, al1, bh.x, bh.y);
            MMA_BF16(c11, ah1, bh.z, bh.w);
            MMA_BF16(c11, ah1, bl.z, bl.w);
            MMA_BF16(c11, al1, bh.z, bh.w);
        }
    }
}

__global__ __launch_bounds__(256, 2) void mlp_mma_kernel(int depth,
                                                         const float* __restrict__ b_in,
                                                         const float* __restrict__ b_out,
                                                         const float* __restrict__ gamma,
                                                         const float* __restrict__ beta) {
    extern __shared__ char smem[];
    const unsigned sb = smem_u32(smem);
    const int tid = threadIdx.x;
    const int wid = tid >> 5, lane = tid & 31;
    const int wr = wid >> 2;              // 0..1 row group (m32)
    const int wc = wid & 3;               // 0..3 col group (n32)
    const int r0 = wr * 32;
    const int n0 = wc * 32;
    const size_t row0 = (size_t)blockIdx.x * 64;

    // ---- load Y -> bf16 hi/lo tiles; stage W_in a-half (rows 0..127) ----
#pragma unroll
    for (int t = 0; t < 16; ++t) {
        int idx = tid + t * 256;          // pair index over 64 x 64
        int r = idx >> 6, kp = idx & 63;
        float2 y2 = *(const float2*)&g_bufB[(row0 + r) * CD + 2 * kp];
        __nv_bfloat16 h0 = __float2bfloat16(y2.x), h1 = __float2bfloat16(y2.y);
        __nv_bfloat16 l0 = __float2bfloat16(y2.x - __bfloat162float(h0));
        __nv_bfloat16 l1 = __float2bfloat16(y2.y - __bfloat162float(h1));
        __nv_bfloat162 hp = __halves2bfloat162(h0, h1);
        __nv_bfloat162 lp = __halves2bfloat162(l0, l1);
        *(unsigned*)(smem + SM_YH + r * 272 + kp * 4) = *(unsigned*)&hp;
        *(unsigned*)(smem + SM_YL + r * 272 + kp * 4) = *(unsigned*)&lp;
    }
    copy_w(smem, tid, g_WinH[depth], g_WinL[depth]);
    __syncthreads();

    const int rA = (lane >> 2);
    const int cB = (lane & 3) * 2;

    // ---- GEMM1 pass A: a-half, kept in registers ----
    float acc_a[2][4][4];
#pragma unroll
    for (int m = 0; m < 2; ++m)
#pragma unroll
        for (int n = 0; n < 4; ++n)
#pragma unroll
            for (int j = 0; j < 4; ++j) acc_a[m][n][j] = 0.f;
    gemm_pass(smem, sb, SM_YH, SM_YL, r0, n0, lane, acc_a);
    __syncthreads();

    // ---- stage W_in g-half (rows 128..255) ----
    copy_w(smem, tid, g_WinH[depth] + 128 * 128, g_WinL[depth] + 128 * 128);
    __syncthreads();

    // ---- GEMM1 pass B: g-half ----
    float acc_g[2][4][4];
#pragma unroll
    for (int m = 0; m < 2; ++m)
#pragma unroll
        for (int n = 0; n < 4; ++n)
#pragma unroll
            for (int j = 0; j < 4; ++j) acc_g[m][n][j] = 0.f;
    gemm_pass(smem, sb, SM_YH, SM_YL, r0, n0, lane, acc_g);
    __syncthreads();          // all Y reads complete before U overwrites Y

    // ---- GLU in regs -> U tiles (overwrite Y region); stage W_out ----
#pragma unroll
    for (int m = 0; m < 2; ++m) {
#pragma unroll
        for (int n = 0; n < 4; ++n) {
            const int col = n0 + n * 8 + cB;
            const float ba0 = __ldg(&b_in[col]),       ba1 = __ldg(&b_in[col + 1]);
            const float bg0 = __ldg(&b_in[128 + col]), bg1 = __ldg(&b_in[128 + col + 1]);
#pragma unroll
            for (int rr = 0; rr < 2; ++rr) {
                const int r = r0 + m * 16 + rA + rr * 8;
                float av0 = acc_a[m][n][rr * 2]     + ba0;
                float av1 = acc_a[m][n][rr * 2 + 1] + ba1;
                float gv0 = acc_g[m][n][rr * 2]     + bg0;
                float gv1 = acc_g[m][n][rr * 2 + 1] + bg1;
                float u0 = av0 / (1.0f + expf(-gv0));
                float u1 = av1 / (1.0f + expf(-gv1));
                __nv_bfloat16 h0 = __float2bfloat16(u0), h1 = __float2bfloat16(u1);
                __nv_bfloat16 l0 = __float2bfloat16(u0 - __bfloat162float(h0));
                __nv_bfloat16 l1 = __float2bfloat16(u1 - __bfloat162float(h1));
                __nv_bfloat162 hp = __halves2bfloat162(h0, h1);
                __nv_bfloat162 lp = __halves2bfloat162(l0, l1);
                *(unsigned*)(smem + SM_UH + r * 272 + col * 2) = *(unsigned*)&hp;
                *(unsigned*)(smem + SM_UL + r * 272 + col * 2) = *(unsigned*)&lp;
            }
        }
    }
    copy_w(smem, tid, g_WoutH[depth], g_WoutL[depth]);
    __syncthreads();

    // ---- GEMM2 ----
    float acc2[2][4][4];
#pragma unroll
    for (int m = 0; m < 2; ++m)
#pragma unroll
        for (int n = 0; n < 4; ++n)
#pragma unroll
            for (int j = 0; j < 4; ++j) acc2[m][n][j] = 0.f;
    gemm_pass(smem, sb, SM_UH, SM_UL, r0, n0, lane, acc2);
    __syncthreads();          // all U reads done; safe to overlay z

    // ---- epilogue: z = acc2 + b_out + residual(global fp32) -> zbuf ----
    float* zbuf = (float*)(smem + SM_ZB);  // [r][132]
#pragma unroll
    for (int m = 0; m < 2; ++m) {
#pragma unroll
        for (int n = 0; n < 4; ++n) {
            const int col = n0 + n * 8 + cB;
            const float bb0 = __ldg(&b_out[col]), bb1 = __ldg(&b_out[col + 1]);
#pragma unroll
            for (int rr = 0; rr < 2; ++rr) {
                const int r = r0 + m * 16 + rA + rr * 8;
                float2 y2 = *(const float2*)&g_bufB[(row0 + r) * CD + col];
                float z0 = acc2[m][n][rr * 2]     + bb0 + y2.x;
                float z1 = acc2[m][n][rr * 2 + 1] + bb1 + y2.y;
                zbuf[r * 132 + col]     = z0;
                zbuf[r * 132 + col + 1] = z1;
            }
        }
    }
    __syncthreads();

    // ---- LayerNorm per row over 128 channels -> g_bufA ----
    for (int r = wid; r < 64; r += 8) {
        float v[4]; float s = 0.f;
#pragma unroll
        for (int i = 0; i < 4; ++i) {
            v[i] = zbuf[r * 132 + lane + i * 32];
            s += v[i];
        }
#pragma unroll
        for (int off = 16; off; off >>= 1) s += __shfl_xor_sync(0xffffffffu, s, off);
        float mu = s * (1.0f / 128.0f);
        float vs = 0.f;
#pragma unroll
        for (int i = 0; i < 4; ++i) { float d = v[i] - mu; vs += d * d; }
#pragma unroll
        for (int off = 16; off; off >>= 1) vs += __shfl_xor_sync(0xffffffffu, vs, off);
        float rstd = rsqrtf(vs * (1.0f / 128.0f) + 1e-5f);
#pragma unroll
        for (int i = 0; i < 4; ++i) {
            int ch = lane + i * 32;
            g_bufA[(row0 + r) * CD + ch] =
                (v[i] - mu) * rstd * __ldg(&gamma[ch]) + __ldg(&beta[ch]);
        }
    }
}

// ---------------- final mean over L ----------------
__global__ __launch_bounds__(512) void mean_kernel(float* __restrict__ out) {
    __shared__ float part[4][128];
    const int b  = blockIdx.x;
    const int c  = threadIdx.x & 127;
    const int lq = threadIdx.x >> 7;
    const float* p = g_bufA + (size_t)b * SEQ * CD + c;
    float s = 0.f;
    for (int l = lq * 128; l < lq * 128 + 128; ++l) s += p[l * CD];
    part[lq][c] = s;
    __syncthreads();
    if (lq == 0)
        out[b * CD + c] = (part[0][c] + part[1][c] + part[2][c] + part[3][c]) * (1.0f / 512.0f);
}

extern "C" void kernel_launch(void* const* d_in, const int* in_sizes, int n_in,
                              void* d_out, int out_size) {
    const float* x     = (const float*)d_in[0];
    const float* Wp    = (const float*)d_in[2];
    const float* bp    = (const float*)d_in[3];
    const float* ltau  = (const float*)d_in[4];
    const float* W_in  = (const float*)d_in[5];
    const float* b_in  = (const float*)d_in[6];
    const float* W_out = (const float*)d_in[7];
    const float* b_out = (const float*)d_in[8];
    const float* gamma = (const float*)d_in[9];
    const float* beta  = (const float*)d_in[10];
    float* out = (float*)d_out;

    cudaFuncSetAttribute(mlp_mma_kernel, cudaFuncAttributeMaxDynamicSharedMemorySize,
                         MMA_SMEM_BYTES);

    stage_w_kernel<<<3, 256>>>(W_in, W_out);
    proj_kernel<<<NTOK / 32, 128>>>(x, Wp, bp);
    for (int d = 0; d < 3; ++d) {
        conv_kernel<<<NGR * 8, 128>>>(ltau + d * 128);
        mlp_mma_kernel<<<NTOK / 64, 256, MMA_SMEM_BYTES>>>(
            d, b_in + d * 256, b_out + d * 128, gamma + d * 128, beta + d * 128);
    }
    mean_kernel<<<NGR, 512>>>(out);
}